// round 4
// baseline (speedup 1.0000x reference)
#include <cuda_runtime.h>
#include <math.h>

// ---------------- problem constants ----------------
#define NFFT   4096
#define NH     2048          // packed complex FFT length
#define NFRQ   2049          // rfft bins
#define BP     128           // t*b = 16*8 segments
#define NC     64            // channels
#define NHF    128           // output heads
#define TT     16            // decimation factor t
#define NB     8             // batch b
#define NSEG   65536         // samples per (b,c)
#define FLT_LEN 1023

// ---------------- scratch (device globals; no allocation allowed) ----------------
__device__ float2 g_U[(size_t)NFRQ * BP * NC];    // [k][b'][c]
__device__ float2 g_V[(size_t)NFRQ * NC * NHF];   // [k][c][h]  (conj filter spectrum)
__device__ float2 g_Y[(size_t)NFRQ * BP * NHF];   // [k][b'][h]
__device__ float  g_T[(size_t)BP * NHF * NFFT];   // staging [b'][h][n]
__device__ float2 g_tw2048[NH];                   // exp(-2pi i j/2048)
__device__ float2 g_tw4096[NH];                   // exp(-2pi i k/4096)

// ---------------- helpers ----------------
__device__ __forceinline__ int PI1(int a) { return a ^ ((a >> 3) & 7); }
__device__ __forceinline__ int PI2(int a) { return a ^ (((a >> 6) & 1) << 3); }

__device__ __forceinline__ float2 cadd(float2 a, float2 b){return make_float2(a.x+b.x, a.y+b.y);}
__device__ __forceinline__ float2 csub(float2 a, float2 b){return make_float2(a.x-b.x, a.y-b.y);}
__device__ __forceinline__ float2 cmulf(float2 a, float2 b){
    return make_float2(fmaf(a.x, b.x, -a.y*b.y), fmaf(a.x, b.y, a.y*b.x));
}
template<int INV> __device__ __forceinline__ float2 mulI(float2 a){
    return INV ? make_float2(-a.y, a.x) : make_float2(a.y, -a.x);
}
template<int INV> __device__ __forceinline__ float2 twld(const float2* __restrict__ t, int i){
    float2 w = __ldg(&t[i]);
    if (INV) w.y = -w.y;
    return w;
}

// DIF radix-8 butterfly. B[j] = sum_l a[l]*w8^(j*l), w8 = exp(sign*i*pi/4)
template<int INV>
__device__ __forceinline__ void dft8(const float2* a, float2* B) {
    const float r = 0.70710678118654752440f;
    float2 e0=cadd(a[0],a[4]), e1=csub(a[0],a[4]);
    float2 e2=cadd(a[2],a[6]), e3=mulI<INV>(csub(a[2],a[6]));
    float2 E0=cadd(e0,e2), E2=csub(e0,e2), E1=cadd(e1,e3), E3=csub(e1,e3);
    float2 o0=cadd(a[1],a[5]), o1=csub(a[1],a[5]);
    float2 o2=cadd(a[3],a[7]), o3=mulI<INV>(csub(a[3],a[7]));
    float2 O0=cadd(o0,o2), O2=csub(o0,o2), O1=cadd(o1,o3), O3=csub(o1,o3);
    float2 w1o, w3o;
    if (!INV) {
        w1o = make_float2(r*(O1.x+O1.y), r*(O1.y-O1.x));
        w3o = make_float2(r*(O3.y-O3.x), -r*(O3.x+O3.y));
    } else {
        w1o = make_float2(r*(O1.x-O1.y), r*(O1.y+O1.x));
        w3o = make_float2(-r*(O3.x+O3.y), r*(O3.x-O3.y));
    }
    float2 w2o = mulI<INV>(O2);
    B[0]=cadd(E0,O0); B[4]=csub(E0,O0);
    B[1]=cadd(E1,w1o); B[5]=csub(E1,w1o);
    B[2]=cadd(E2,w2o); B[6]=csub(E2,w2o);
    B[3]=cadd(E3,w3o); B[7]=csub(E3,w3o);
}

// Stockham DIF FFT, N=2048 = 8*8*8*4, 256 threads.
template<int INV>
__device__ void fft2048_r8(float2* b1, float2* b2, const float2* __restrict__ twg, int tid) {
    {
        float2 a[8], B[8];
        #pragma unroll
        for (int j=0;j<8;j++) a[j] = b2[PI2(tid + (j<<8))];
        dft8<INV>(a,B);
        #pragma unroll
        for (int j=1;j<8;j++) B[j] = cmulf(B[j], twld<INV>(twg, j*tid));
        #pragma unroll
        for (int j=0;j<8;j++) b1[PI1((tid<<3) + j)] = B[j];
    }
    __syncthreads();
    {
        float2 a[8], B[8];
        #pragma unroll
        for (int j=0;j<8;j++) a[j] = b1[PI1(tid + (j<<8))];
        dft8<INV>(a,B);
        const int p = tid>>3, q = tid&7, ps = p<<3, base = q + (p<<6);
        #pragma unroll
        for (int j=1;j<8;j++) B[j] = cmulf(B[j], twld<INV>(twg, j*ps));
        #pragma unroll
        for (int j=0;j<8;j++) b2[PI2(base + (j<<3))] = B[j];
    }
    __syncthreads();
    {
        float2 a[8], B[8];
        #pragma unroll
        for (int j=0;j<8;j++) a[j] = b2[PI2(tid + (j<<8))];
        dft8<INV>(a,B);
        const int p = tid>>6, q = tid&63, ps = p<<6, base = q + (p<<9);
        #pragma unroll
        for (int j=1;j<8;j++) B[j] = cmulf(B[j], twld<INV>(twg, j*ps));
        #pragma unroll
        for (int j=0;j<8;j++) b1[PI1(base + (j<<6))] = B[j];
    }
    __syncthreads();
    #pragma unroll
    for (int e=0;e<2;e++) {
        const int idx = tid + (e<<8);
        float2 c0=b1[PI1(idx)], c1=b1[PI1(idx+512)], c2=b1[PI1(idx+1024)], c3=b1[PI1(idx+1536)];
        float2 t0=cadd(c0,c2), t1=csub(c0,c2);
        float2 t2=cadd(c1,c3), t3=mulI<INV>(csub(c1,c3));
        b2[PI2(idx)]      = cadd(t0,t2);
        b2[PI2(idx+512)]  = cadd(t1,t3);
        b2[PI2(idx+1024)] = csub(t0,t2);
        b2[PI2(idx+1536)] = csub(t1,t3);
    }
    __syncthreads();
}

// ---------------- kernel 0: twiddle tables ----------------
__global__ void k_twid() {
    int i = blockIdx.x * 256 + threadIdx.x;
    float s, c;
    if (i < NH) {
        sincospif(-(float)i / 1024.0f, &s, &c);
        g_tw2048[i] = make_float2(c, s);
    } else {
        int k = i - NH;
        sincospif(-(float)k / 2048.0f, &s, &c);
        g_tw4096[k] = make_float2(c, s);
    }
}

// ---------------- kernel 1: forward rfft of decimated X (4 channels per block) ----------------
__global__ __launch_bounds__(256) void k_fwd_x(const float* __restrict__ X) {
    __shared__ float2 b1[NH];
    __shared__ float2 b2[NH];
    const int tid = threadIdx.x;
    const int blk = blockIdx.x;            // ((bi*16 + cq)<<4) + ti
    const int ti  = blk & 15;
    const int bcq = blk >> 4;
    const int cq  = bcq & 15;
    const int bi  = bcq >> 4;
    const int bp  = ti * NB + bi;
    #pragma unroll 1
    for (int cc = 0; cc < 4; cc++) {
        const int ci = cq * 4 + cc;
        const float* row = X + (size_t)(bi * NC + ci) * NSEG;
        for (int n = tid; n < NH; n += 256) {
            float e = __ldg(row + (n << 5) + ti);
            float o = __ldg(row + (n << 5) + 16 + ti);
            b2[PI2(n)] = make_float2(e, o);
        }
        __syncthreads();
        fft2048_r8<0>(b1, b2, g_tw2048, tid);
        const size_t base = (size_t)bp * NC + ci;
        for (int k = tid; k < NH; k += 256) {
            float2 Zk = b2[PI2(k)];
            float2 Zc = b2[PI2((NH - k) & (NH - 1))];
            Zc.y = -Zc.y;
            float2 Xe = make_float2(0.5f*(Zk.x+Zc.x), 0.5f*(Zk.y+Zc.y));
            float dx = Zk.x - Zc.x, dy = Zk.y - Zc.y;
            float2 Xo = make_float2(0.5f*dy, -0.5f*dx);
            float2 W = __ldg(&g_tw4096[k]);
            float2 WXo = cmulf(W, Xo);
            g_U[(size_t)k * (BP*NC) + base] = make_float2(Xe.x + WXo.x, Xe.y + WXo.y);
            if (k == 0)
                g_U[(size_t)NH * (BP*NC) + base] = make_float2(Zk.x - Zk.y, 0.0f);
        }
        __syncthreads();
    }
}

// ---------------- kernel 2: conj(rfft(filters)) -> [k][c][h]  (4 heads per block) ----------------
__global__ __launch_bounds__(256) void k_fwd_f(const float* __restrict__ F) {
    __shared__ float2 b1[NH];
    __shared__ float2 b2[NH];
    const int tid = threadIdx.x;
    const int blk = blockIdx.x;            // ci*32 + hq
    const int hq = blk & 31;
    const int ci = blk >> 5;
    #pragma unroll 1
    for (int hh = 0; hh < 4; hh++) {
        const int hi = hq * 4 + hh;
        const float* row = F + (size_t)(hi * NC + ci) * FLT_LEN;
        for (int n = tid; n < NH; n += 256) {
            int i0 = 2*n, i1 = 2*n + 1;
            float e = (i0 < FLT_LEN) ? __ldg(row + i0) : 0.0f;
            float o = (i1 < FLT_LEN) ? __ldg(row + i1) : 0.0f;
            b2[PI2(n)] = make_float2(e, o);
        }
        __syncthreads();
        fft2048_r8<0>(b1, b2, g_tw2048, tid);
        const size_t base = (size_t)ci * NHF + hi;
        for (int k = tid; k < NH; k += 256) {
            float2 Zk = b2[PI2(k)];
            float2 Zc = b2[PI2((NH - k) & (NH - 1))];
            Zc.y = -Zc.y;
            float2 Xe = make_float2(0.5f*(Zk.x+Zc.x), 0.5f*(Zk.y+Zc.y));
            float dx = Zk.x - Zc.x, dy = Zk.y - Zc.y;
            float2 Xo = make_float2(0.5f*dy, -0.5f*dx);
            float2 W = __ldg(&g_tw4096[k]);
            float2 WXo = cmulf(W, Xo);
            g_V[(size_t)k * (NC*NHF) + base] = make_float2(Xe.x + WXo.x, -(Xe.y + WXo.y));
            if (k == 0)
                g_V[(size_t)NH * (NC*NHF) + base] = make_float2(Zk.x - Zk.y, 0.0f);
        }
        __syncthreads();
    }
}

// ---------------- kernel 3: per-frequency complex GEMM via fma.rn.f32x2 ----------------
// acc(y.x,y.y) += splat(a.x)*(vx,vy) + splat(a.y)*(-vy,vx). V staged in smem (both forms).
__device__ __forceinline__ unsigned long long splat2(float x) {
    unsigned long long r;
    asm("mov.b64 %0, {%1, %1};" : "=l"(r) : "f"(x));
    return r;
}
__device__ __forceinline__ void fma2(unsigned long long& d, unsigned long long a, unsigned long long b) {
    asm("fma.rn.f32x2 %0, %1, %2, %0;" : "+l"(d) : "l"(a), "l"(b));
}

#define CK 8   // channels per smem chunk

__global__ __launch_bounds__(256, 2) void k_gemm() {
    __shared__ float2 sU[64 * 65];           // [c][brow] padded
    __shared__ float2 sVr[CK * 128];         // (vx, vy)
    __shared__ float2 sVs[CK * 128];         // (-vy, vx)
    const int k = blockIdx.y;
    const int half = blockIdx.x;
    const int tid = threadIdx.x;
    const int tx = tid & 15, ty = tid >> 4;

    // stage U (transposed, padded)
    const float2* Uk = g_U + (size_t)k * (BP*NC) + (size_t)half * (64*NC);
    #pragma unroll
    for (int r = 0; r < 16; r++) {
        int i = tid + (r << 8);
        int brow = i >> 6, c = i & 63;
        sU[c * 65 + brow] = __ldg(&Uk[i]);
    }

    // V chunk prefetch (registers): chunk = CK rows of 128 complex = 512 float4
    const float4* Vk = (const float4*)(g_V + (size_t)k * (NC*NHF));
    float4 p0 = __ldg(&Vk[tid * 2]);
    float4 p1 = __ldg(&Vk[tid * 2 + 1]);

    unsigned long long acc[4][8];
    #pragma unroll
    for (int i = 0; i < 4; i++)
        #pragma unroll
        for (int j = 0; j < 8; j++) acc[i][j] = 0ull;

    #pragma unroll 1
    for (int ch = 0; ch < NC / CK; ch++) {
        __syncthreads();                       // chunk buffer free (and U staged, 1st iter)
        {
            const int i0 = tid * 4;            // complex index within chunk
            sVr[i0]     = make_float2(p0.x, p0.y);
            sVr[i0 + 1] = make_float2(p0.z, p0.w);
            sVr[i0 + 2] = make_float2(p1.x, p1.y);
            sVr[i0 + 3] = make_float2(p1.z, p1.w);
            sVs[i0]     = make_float2(-p0.y, p0.x);
            sVs[i0 + 1] = make_float2(-p0.w, p0.z);
            sVs[i0 + 2] = make_float2(-p1.y, p1.x);
            sVs[i0 + 3] = make_float2(-p1.w, p1.z);
        }
        __syncthreads();
        if (ch < NC / CK - 1) {
            p0 = __ldg(&Vk[(ch + 1) * 512 + tid * 2]);
            p1 = __ldg(&Vk[(ch + 1) * 512 + tid * 2 + 1]);
        }
        #pragma unroll
        for (int cc = 0; cc < CK; cc++) {
            const int c = ch * CK + cc;
            unsigned long long ax[4], ay[4];
            #pragma unroll
            for (int i = 0; i < 4; i++) {
                float2 a = sU[c * 65 + ty + (i << 4)];
                ax[i] = splat2(a.x);
                ay[i] = splat2(a.y);
            }
            #pragma unroll
            for (int j = 0; j < 8; j++) {
                unsigned long long br = *(const unsigned long long*)&sVr[cc * 128 + tx + (j << 4)];
                unsigned long long bs = *(const unsigned long long*)&sVs[cc * 128 + tx + (j << 4)];
                #pragma unroll
                for (int i = 0; i < 4; i++) {
                    fma2(acc[i][j], ax[i], br);
                    fma2(acc[i][j], ay[i], bs);
                }
            }
        }
    }

    float2* Yk = g_Y + (size_t)k * (BP*NHF) + (size_t)half * (64*NHF);
    #pragma unroll
    for (int i = 0; i < 4; i++) {
        int row = ty + (i << 4);
        #pragma unroll
        for (int j = 0; j < 8; j++) {
            float rx, ry;
            asm("mov.b64 {%0, %1}, %2;" : "=f"(rx), "=f"(ry) : "l"(acc[i][j]));
            Yk[row * NHF + tx + (j << 4)] = make_float2(rx, ry);
        }
    }
}

// ---------------- kernel 4: irfft + |.| + log1p + InstanceNorm -> staging (4 heads/block) ----------------
__global__ __launch_bounds__(256) void k_inv() {
    __shared__ float2 b1[NH];
    __shared__ float2 b2[NH];
    __shared__ float rs[8], rq[8];
    __shared__ float sMean, sScale;
    const int tid = threadIdx.x;
    const int blk = blockIdx.x;            // bp*32 + hq
    const int hq = blk & 31;
    const int bp = blk >> 5;

    #pragma unroll 1
    for (int hh = 0; hh < 4; hh++) {
        const int hi = hq * 4 + hh;
        const float2* Ycol = g_Y + (size_t)bp * NHF + hi;
        for (int k = tid; k < NH; k += 256) {
            float2 Yk = __ldg(&Ycol[(size_t)k * (BP*NHF)]);
            float2 Ym = __ldg(&Ycol[(size_t)(NH - k) * (BP*NHF)]);
            Ym.y = -Ym.y;
            float2 Xe = make_float2(0.5f*(Yk.x+Ym.x), 0.5f*(Yk.y+Ym.y));
            float dx = Yk.x - Ym.x, dy = Yk.y - Ym.y;
            float2 t = __ldg(&g_tw4096[k]);
            float c = t.x, s = -t.y;
            float Xox = 0.5f * (c*dx - s*dy);
            float Xoy = 0.5f * (c*dy + s*dx);
            b2[PI2(k)] = make_float2(Xe.x - Xoy, Xe.y + Xox);
        }
        __syncthreads();
        fft2048_r8<1>(b1, b2, g_tw2048, tid);
        float* val = (float*)b1;

        const float inv = 1.0f / 2048.0f;
        float lsum = 0.0f, lsq = 0.0f;
        for (int n = tid; n < NH; n += 256) {
            float2 zz = b2[PI2(n)];
            float v0 = __logf(1.0f + fabsf(zz.x * inv));
            float v1 = __logf(1.0f + fabsf(zz.y * inv));
            b1[n] = make_float2(v0, v1);
            lsum += v0 + v1;
            lsq = fmaf(v0, v0, lsq);
            lsq = fmaf(v1, v1, lsq);
        }
        #pragma unroll
        for (int o = 16; o; o >>= 1) {
            lsum += __shfl_xor_sync(0xffffffffu, lsum, o);
            lsq  += __shfl_xor_sync(0xffffffffu, lsq, o);
        }
        if ((tid & 31) == 0) { rs[tid >> 5] = lsum; rq[tid >> 5] = lsq; }
        __syncthreads();
        if (tid == 0) {
            float s = 0.0f, q = 0.0f;
            #pragma unroll
            for (int i = 0; i < 8; i++) { s += rs[i]; q += rq[i]; }
            float mean = s * (1.0f / 4096.0f);
            float var = q * (1.0f / 4096.0f) - mean * mean;
            sMean = mean;
            sScale = rsqrtf(var + 1e-5f);
        }
        __syncthreads();
        const float mean = sMean, scale = sScale;
        float* orow = g_T + ((size_t)(bp * NHF + hi) << 12);
        for (int n = tid; n < NFFT; n += 256)
            orow[n] = (val[n] - mean) * scale;
        __syncthreads();
    }
}

// ---------------- kernel 5: (t b) h n -> b h (n t), coalesced both sides via smem ----------------
__global__ __launch_bounds__(256) void k_out(float* __restrict__ out) {
    __shared__ float s[256 * 17];
    const int tid = threadIdx.x;
    const int blk = blockIdx.x;            // ((bi*128 + hi)<<4) + nc
    const int nc = blk & 15;
    const int bh = blk >> 4;               // bi*128 + hi
    const int hi = bh & (NHF - 1);
    const int bi = bh >> 7;
    #pragma unroll
    for (int ti = 0; ti < 16; ti++) {
        s[tid * 17 + ti] = g_T[((size_t)((ti * NB + bi) * NHF + hi) << 12) + nc * 256 + tid];
    }
    __syncthreads();
    float* obase = out + (size_t)bh * NSEG + nc * 4096;
    #pragma unroll
    for (int i = 0; i < 16; i++) {
        int u = tid + (i << 8);
        obase[u] = s[(u >> 4) * 17 + (u & 15)];
    }
}

// ---------------- launch ----------------
extern "C" void kernel_launch(void* const* d_in, const int* in_sizes, int n_in,
                              void* d_out, int out_size) {
    const float* X = (const float*)d_in[0];
    const float* F = (const float*)d_in[1];
    if (n_in >= 2 && in_sizes[0] < in_sizes[1]) {
        const float* t = X; X = F; F = t;
    }
    float* out = (float*)d_out;

    k_twid<<<16, 256>>>();
    k_fwd_x<<<NB * 16 * 16, 256>>>(X);            // 2048 blocks x 4 FFTs
    k_fwd_f<<<NC * 32, 256>>>(F);                 // 2048 blocks x 4 FFTs
    k_gemm<<<dim3(2, NFRQ), 256>>>();             // 4098 blocks
    k_inv<<<BP * 32, 256>>>();                    // 4096 blocks x 4 iFFTs
    k_out<<<NB * NHF * 16, 256>>>(out);           // 16384 blocks
}

// round 5
// speedup vs baseline: 1.2164x; 1.2164x over previous
#include <cuda_runtime.h>
#include <math.h>

// ---------------- problem constants ----------------
#define NFFT   4096
#define NH     2048
#define NFRQ   2049
#define BP     128
#define NC     64
#define NHF    128
#define TT     16
#define NB     8
#define NSEG   65536
#define FLT_LEN 1023

// ---------------- scratch ----------------
__device__ float2 g_U[(size_t)NFRQ * BP * NC];    // [k][b'][c]
__device__ float2 g_V[(size_t)NFRQ * NC * NHF];   // [k][c][h] (conj)
__device__ float2 g_Y[(size_t)NFRQ * BP * NHF];   // [k][b'][h]
__device__ float  g_T[(size_t)BP * NHF * NFFT];   // staging [b'][h][n]
__device__ float2 g_tw2048[NH];
__device__ float2 g_tw4096[NH];

// ---------------- helpers ----------------
// swizzled index for interleaved-4 buffers: float2 slot for (k, s)
__device__ __forceinline__ int SW(int k, int s) {
    int x = ((k >> 2) ^ (k >> 6)) & 1;                 // -> bit0
    x |= (((k >> 3) ^ (k >> 6)) & 1) << 1;             // -> bit1
    x |= (((k >> 3) ^ (k >> 5)) & 1) << 2;             // -> bit2
    x |= (((k >> 4) ^ (k >> 6)) & 1) << 3;             // -> bit3
    return ((k << 2) | s) ^ x;
}

__device__ __forceinline__ float2 cadd(float2 a, float2 b){return make_float2(a.x+b.x, a.y+b.y);}
__device__ __forceinline__ float2 csub(float2 a, float2 b){return make_float2(a.x-b.x, a.y-b.y);}
__device__ __forceinline__ float2 cmulf(float2 a, float2 b){
    return make_float2(fmaf(a.x, b.x, -a.y*b.y), fmaf(a.x, b.y, a.y*b.x));
}
template<int INV> __device__ __forceinline__ float2 mulI(float2 a){
    return INV ? make_float2(-a.y, a.x) : make_float2(a.y, -a.x);
}
template<int INV> __device__ __forceinline__ float2 twld(const float2* __restrict__ t, int i){
    float2 w = __ldg(&t[i]);
    if (INV) w.y = -w.y;
    return w;
}

template<int INV>
__device__ __forceinline__ void dft8(const float2* a, float2* B) {
    const float r = 0.70710678118654752440f;
    float2 e0=cadd(a[0],a[4]), e1=csub(a[0],a[4]);
    float2 e2=cadd(a[2],a[6]), e3=mulI<INV>(csub(a[2],a[6]));
    float2 E0=cadd(e0,e2), E2=csub(e0,e2), E1=cadd(e1,e3), E3=csub(e1,e3);
    float2 o0=cadd(a[1],a[5]), o1=csub(a[1],a[5]);
    float2 o2=cadd(a[3],a[7]), o3=mulI<INV>(csub(a[3],a[7]));
    float2 O0=cadd(o0,o2), O2=csub(o0,o2), O1=cadd(o1,o3), O3=csub(o1,o3);
    float2 w1o, w3o;
    if (!INV) {
        w1o = make_float2(r*(O1.x+O1.y), r*(O1.y-O1.x));
        w3o = make_float2(r*(O3.y-O3.x), -r*(O3.x+O3.y));
    } else {
        w1o = make_float2(r*(O1.x-O1.y), r*(O1.y+O1.x));
        w3o = make_float2(-r*(O3.x+O3.y), r*(O3.x-O3.y));
    }
    float2 w2o = mulI<INV>(O2);
    B[0]=cadd(E0,O0); B[4]=csub(E0,O0);
    B[1]=cadd(E1,w1o); B[5]=csub(E1,w1o);
    B[2]=cadd(E2,w2o); B[6]=csub(E2,w2o);
    B[3]=cadd(E3,w3o); B[7]=csub(E3,w3o);
}

// Interleaved x4 Stockham FFT, N=2048=8*8*8*4, 256 threads.
// Input in bA at SW(n,s). Output in bA at SW(k,s), natural order.
template<int INV>
__device__ void fft2048x4(float2* bA, float2* bB, const float2* __restrict__ twg, int tid) {
    { // S0: A->B  read tid+256j, write 8*tid+j, tw j*tid
        float2 w[7];
        #pragma unroll
        for (int j=1;j<8;j++) w[j-1] = twld<INV>(twg, j*tid);
        #pragma unroll
        for (int s=0;s<4;s++) {
            float2 a[8], B[8];
            #pragma unroll
            for (int j=0;j<8;j++) a[j] = bA[SW(tid + (j<<8), s)];
            dft8<INV>(a,B);
            #pragma unroll
            for (int j=1;j<8;j++) B[j] = cmulf(B[j], w[j-1]);
            #pragma unroll
            for (int j=0;j<8;j++) bB[SW((tid<<3) + j, s)] = B[j];
        }
    }
    __syncthreads();
    { // S1: B->A  write q+64p+8j, tw j*8p
        const int p = tid>>3, q = tid&7, ps = p<<3, base = q + (p<<6);
        float2 w[7];
        #pragma unroll
        for (int j=1;j<8;j++) w[j-1] = twld<INV>(twg, j*ps);
        #pragma unroll
        for (int s=0;s<4;s++) {
            float2 a[8], B[8];
            #pragma unroll
            for (int j=0;j<8;j++) a[j] = bB[SW(tid + (j<<8), s)];
            dft8<INV>(a,B);
            #pragma unroll
            for (int j=1;j<8;j++) B[j] = cmulf(B[j], w[j-1]);
            #pragma unroll
            for (int j=0;j<8;j++) bA[SW(base + (j<<3), s)] = B[j];
        }
    }
    __syncthreads();
    { // S2: A->B  write q+512p+64j, tw j*64p
        const int p = tid>>6, q = tid&63, ps = p<<6, base = q + (p<<9);
        float2 w[7];
        #pragma unroll
        for (int j=1;j<8;j++) w[j-1] = twld<INV>(twg, j*ps);
        #pragma unroll
        for (int s=0;s<4;s++) {
            float2 a[8], B[8];
            #pragma unroll
            for (int j=0;j<8;j++) a[j] = bA[SW(tid + (j<<8), s)];
            dft8<INV>(a,B);
            #pragma unroll
            for (int j=1;j<8;j++) B[j] = cmulf(B[j], w[j-1]);
            #pragma unroll
            for (int j=0;j<8;j++) bB[SW(base + (j<<6), s)] = B[j];
        }
    }
    __syncthreads();
    // S3: radix-4 B->A (no twiddles)
    #pragma unroll
    for (int e=0;e<2;e++) {
        const int idx = tid + (e<<8);
        #pragma unroll
        for (int s=0;s<4;s++) {
            float2 c0=bB[SW(idx,s)], c1=bB[SW(idx+512,s)], c2=bB[SW(idx+1024,s)], c3=bB[SW(idx+1536,s)];
            float2 t0=cadd(c0,c2), t1=csub(c0,c2);
            float2 t2=cadd(c1,c3), t3=mulI<INV>(csub(c1,c3));
            bA[SW(idx,s)]      = cadd(t0,t2);
            bA[SW(idx+512,s)]  = cadd(t1,t3);
            bA[SW(idx+1024,s)] = csub(t0,t2);
            bA[SW(idx+1536,s)] = csub(t1,t3);
        }
    }
    __syncthreads();
}

// rfft post-combine: given Z[k], Z[(N-k)%N] of packed FFT -> U[k]
__device__ __forceinline__ float2 rpost(float2 Zk, float2 Zc, float2 W) {
    Zc.y = -Zc.y;
    float2 Xe = make_float2(0.5f*(Zk.x+Zc.x), 0.5f*(Zk.y+Zc.y));
    float dx = Zk.x - Zc.x, dy = Zk.y - Zc.y;
    float2 Xo = make_float2(0.5f*dy, -0.5f*dx);
    float2 WXo = cmulf(W, Xo);
    return make_float2(Xe.x + WXo.x, Xe.y + WXo.y);
}

// ---------------- kernel 0: twiddles ----------------
__global__ void k_twid() {
    int i = blockIdx.x * 256 + threadIdx.x;
    float s, c;
    if (i < NH) {
        sincospif(-(float)i / 1024.0f, &s, &c);
        g_tw2048[i] = make_float2(c, s);
    } else {
        int k = i - NH;
        sincospif(-(float)k / 2048.0f, &s, &c);
        g_tw4096[k] = make_float2(c, s);
    }
}

// ---------------- kernel 1: forward rfft of X, 4 channels interleaved ----------------
__global__ __launch_bounds__(256) void k_fwd_x(const float* __restrict__ X) {
    extern __shared__ float2 dsm[];
    float2* bA = dsm;
    float2* bB = dsm + 8192;
    const int tid = threadIdx.x;
    const int blk = blockIdx.x;            // ((bi*16 + cq)<<4) + ti
    const int ti  = blk & 15;
    const int bcq = blk >> 4;
    const int cq  = bcq & 15;
    const int bi  = bcq >> 4;
    const int bp  = ti * NB + bi;
    const int ci0 = cq * 4;
    const float* base = X + (size_t)(bi * NC + ci0) * NSEG;

    #pragma unroll
    for (int r = 0; r < 8; r++) {
        int n = tid + (r << 8);
        int off = (n << 5) + ti;
        #pragma unroll
        for (int s = 0; s < 4; s++) {
            float e = __ldg(base + (size_t)s * NSEG + off);
            float o = __ldg(base + (size_t)s * NSEG + off + 16);
            bA[SW(n, s)] = make_float2(e, o);
        }
    }
    __syncthreads();
    fft2048x4<0>(bA, bB, g_tw2048, tid);

    const size_t gbase = (size_t)bp * NC + ci0;
    #pragma unroll
    for (int r = 0; r < 8; r++) {
        int k = tid + (r << 8);
        int km = (NH - k) & (NH - 1);
        float2 W = __ldg(&g_tw4096[k]);
        float2 v[4];
        #pragma unroll
        for (int s = 0; s < 4; s++)
            v[s] = rpost(bA[SW(k, s)], bA[SW(km, s)], W);
        float4* dst = (float4*)(g_U + (size_t)k * (BP*NC) + gbase);
        dst[0] = make_float4(v[0].x, v[0].y, v[1].x, v[1].y);
        dst[1] = make_float4(v[2].x, v[2].y, v[3].x, v[3].y);
        if (k == 0) {
            float2 nv[4];
            #pragma unroll
            for (int s = 0; s < 4; s++) {
                float2 Z0 = bA[SW(0, s)];
                nv[s] = make_float2(Z0.x - Z0.y, 0.0f);
            }
            float4* nd = (float4*)(g_U + (size_t)NH * (BP*NC) + gbase);
            nd[0] = make_float4(nv[0].x, nv[0].y, nv[1].x, nv[1].y);
            nd[1] = make_float4(nv[2].x, nv[2].y, nv[3].x, nv[3].y);
        }
    }
}

// ---------------- kernel 2: conj(rfft(filters)), 4 heads interleaved ----------------
__global__ __launch_bounds__(256) void k_fwd_f(const float* __restrict__ F) {
    extern __shared__ float2 dsm[];
    float2* bA = dsm;
    float2* bB = dsm + 8192;
    const int tid = threadIdx.x;
    const int blk = blockIdx.x;            // ci*32 + hq
    const int hq = blk & 31;
    const int ci = blk >> 5;
    const int hi0 = hq * 4;

    #pragma unroll
    for (int r = 0; r < 8; r++) {
        int n = tid + (r << 8);
        int i0 = 2 * n, i1 = 2 * n + 1;
        #pragma unroll
        for (int s = 0; s < 4; s++) {
            const float* row = F + ((size_t)(hi0 + s) * NC + ci) * FLT_LEN;
            float e = (i0 < FLT_LEN) ? __ldg(row + i0) : 0.0f;
            float o = (i1 < FLT_LEN) ? __ldg(row + i1) : 0.0f;
            bA[SW(n, s)] = make_float2(e, o);
        }
    }
    __syncthreads();
    fft2048x4<0>(bA, bB, g_tw2048, tid);

    const size_t gbase = (size_t)ci * NHF + hi0;
    #pragma unroll
    for (int r = 0; r < 8; r++) {
        int k = tid + (r << 8);
        int km = (NH - k) & (NH - 1);
        float2 W = __ldg(&g_tw4096[k]);
        float2 v[4];
        #pragma unroll
        for (int s = 0; s < 4; s++) {
            float2 u = rpost(bA[SW(k, s)], bA[SW(km, s)], W);
            v[s] = make_float2(u.x, -u.y);     // conj
        }
        float4* dst = (float4*)(g_V + (size_t)k * (NC*NHF) + gbase);
        dst[0] = make_float4(v[0].x, v[0].y, v[1].x, v[1].y);
        dst[1] = make_float4(v[2].x, v[2].y, v[3].x, v[3].y);
        if (k == 0) {
            float2 nv[4];
            #pragma unroll
            for (int s = 0; s < 4; s++) {
                float2 Z0 = bA[SW(0, s)];
                nv[s] = make_float2(Z0.x - Z0.y, 0.0f);
            }
            float4* nd = (float4*)(g_V + (size_t)NH * (NC*NHF) + gbase);
            nd[0] = make_float4(nv[0].x, nv[0].y, nv[1].x, nv[1].y);
            nd[1] = make_float4(nv[2].x, nv[2].y, nv[3].x, nv[3].y);
        }
    }
}

// ---------------- kernel 3: per-frequency complex GEMM (unchanged) ----------------
__device__ __forceinline__ unsigned long long splat2(float x) {
    unsigned long long r;
    asm("mov.b64 %0, {%1, %1};" : "=l"(r) : "f"(x));
    return r;
}
__device__ __forceinline__ void fma2(unsigned long long& d, unsigned long long a, unsigned long long b) {
    asm("fma.rn.f32x2 %0, %1, %2, %0;" : "+l"(d) : "l"(a), "l"(b));
}
#define CK 8

__global__ __launch_bounds__(256, 2) void k_gemm() {
    __shared__ float2 sU[64 * 65];
    __shared__ float2 sVr[CK * 128];
    __shared__ float2 sVs[CK * 128];
    const int k = blockIdx.y;
    const int half = blockIdx.x;
    const int tid = threadIdx.x;
    const int tx = tid & 15, ty = tid >> 4;

    const float2* Uk = g_U + (size_t)k * (BP*NC) + (size_t)half * (64*NC);
    #pragma unroll
    for (int r = 0; r < 16; r++) {
        int i = tid + (r << 8);
        int brow = i >> 6, c = i & 63;
        sU[c * 65 + brow] = __ldg(&Uk[i]);
    }

    const float4* Vk = (const float4*)(g_V + (size_t)k * (NC*NHF));
    float4 p0 = __ldg(&Vk[tid * 2]);
    float4 p1 = __ldg(&Vk[tid * 2 + 1]);

    unsigned long long acc[4][8];
    #pragma unroll
    for (int i = 0; i < 4; i++)
        #pragma unroll
        for (int j = 0; j < 8; j++) acc[i][j] = 0ull;

    #pragma unroll 1
    for (int ch = 0; ch < NC / CK; ch++) {
        __syncthreads();
        {
            const int i0 = tid * 4;
            sVr[i0]     = make_float2(p0.x, p0.y);
            sVr[i0 + 1] = make_float2(p0.z, p0.w);
            sVr[i0 + 2] = make_float2(p1.x, p1.y);
            sVr[i0 + 3] = make_float2(p1.z, p1.w);
            sVs[i0]     = make_float2(-p0.y, p0.x);
            sVs[i0 + 1] = make_float2(-p0.w, p0.z);
            sVs[i0 + 2] = make_float2(-p1.y, p1.x);
            sVs[i0 + 3] = make_float2(-p1.w, p1.z);
        }
        __syncthreads();
        if (ch < NC / CK - 1) {
            p0 = __ldg(&Vk[(ch + 1) * 512 + tid * 2]);
            p1 = __ldg(&Vk[(ch + 1) * 512 + tid * 2 + 1]);
        }
        #pragma unroll
        for (int cc = 0; cc < CK; cc++) {
            const int c = ch * CK + cc;
            unsigned long long ax[4], ay[4];
            #pragma unroll
            for (int i = 0; i < 4; i++) {
                float2 a = sU[c * 65 + ty + (i << 4)];
                ax[i] = splat2(a.x);
                ay[i] = splat2(a.y);
            }
            #pragma unroll
            for (int j = 0; j < 8; j++) {
                unsigned long long br = *(const unsigned long long*)&sVr[cc * 128 + tx + (j << 4)];
                unsigned long long bs = *(const unsigned long long*)&sVs[cc * 128 + tx + (j << 4)];
                #pragma unroll
                for (int i = 0; i < 4; i++) {
                    fma2(acc[i][j], ax[i], br);
                    fma2(acc[i][j], ay[i], bs);
                }
            }
        }
    }

    float2* Yk = g_Y + (size_t)k * (BP*NHF) + (size_t)half * (64*NHF);
    #pragma unroll
    for (int i = 0; i < 4; i++) {
        int row = ty + (i << 4);
        #pragma unroll
        for (int j = 0; j < 8; j++) {
            float rx, ry;
            asm("mov.b64 {%0, %1}, %2;" : "=f"(rx), "=f"(ry) : "l"(acc[i][j]));
            Yk[row * NHF + tx + (j << 4)] = make_float2(rx, ry);
        }
    }
}

// ---------------- kernel 4: irfft + log1p + InstanceNorm, 4 heads interleaved ----------------
__global__ __launch_bounds__(256) void k_inv() {
    extern __shared__ float2 dsm[];
    float2* bA = dsm;
    float2* bB = dsm + 8192;
    __shared__ float rs[8][4], rq[8][4];
    __shared__ float sM[4], sS[4];
    const int tid = threadIdx.x;
    const int blk = blockIdx.x;            // bp*32 + hq
    const int hq = blk & 31;
    const int bp = blk >> 5;
    const int hi0 = hq * 4;

    const float2* Ybase = g_Y + (size_t)bp * NHF + hi0;
    #pragma unroll
    for (int r = 0; r < 8; r++) {
        int k = tid + (r << 8);
        const float4* Yk4 = (const float4*)(Ybase + (size_t)k * (BP*NHF));
        const float4* Ym4 = (const float4*)(Ybase + (size_t)(NH - k) * (BP*NHF));
        float4 a0 = __ldg(&Yk4[0]), a1 = __ldg(&Yk4[1]);
        float4 m0 = __ldg(&Ym4[0]), m1 = __ldg(&Ym4[1]);
        float2 t = __ldg(&g_tw4096[k]);
        float c = t.x, sn = -t.y;              // exp(+2pi i k/4096)
        float2 Yk[4] = { make_float2(a0.x,a0.y), make_float2(a0.z,a0.w),
                         make_float2(a1.x,a1.y), make_float2(a1.z,a1.w) };
        float2 Ym[4] = { make_float2(m0.x,m0.y), make_float2(m0.z,m0.w),
                         make_float2(m1.x,m1.y), make_float2(m1.z,m1.w) };
        #pragma unroll
        for (int s = 0; s < 4; s++) {
            float2 yk = Yk[s], ym = Ym[s];
            ym.y = -ym.y;
            float2 Xe = make_float2(0.5f*(yk.x+ym.x), 0.5f*(yk.y+ym.y));
            float dx = yk.x - ym.x, dy = yk.y - ym.y;
            float Xox = 0.5f * (c*dx - sn*dy);
            float Xoy = 0.5f * (c*dy + sn*dx);
            bA[SW(k, s)] = make_float2(Xe.x - Xoy, Xe.y + Xox);
        }
    }
    __syncthreads();
    fft2048x4<1>(bA, bB, g_tw2048, tid);

    const float inv = 1.0f / 2048.0f;
    float ls[4] = {0,0,0,0}, lq[4] = {0,0,0,0};
    #pragma unroll
    for (int r = 0; r < 8; r++) {
        int n = tid + (r << 8);
        #pragma unroll
        for (int s = 0; s < 4; s++) {
            float2 zz = bA[SW(n, s)];
            float v0 = __logf(1.0f + fabsf(zz.x * inv));
            float v1 = __logf(1.0f + fabsf(zz.y * inv));
            bB[SW(n, s)] = make_float2(v0, v1);
            ls[s] += v0 + v1;
            lq[s] = fmaf(v0, v0, lq[s]);
            lq[s] = fmaf(v1, v1, lq[s]);
        }
    }
    #pragma unroll
    for (int o = 16; o; o >>= 1) {
        #pragma unroll
        for (int s = 0; s < 4; s++) {
            ls[s] += __shfl_xor_sync(0xffffffffu, ls[s], o);
            lq[s] += __shfl_xor_sync(0xffffffffu, lq[s], o);
        }
    }
    if ((tid & 31) == 0) {
        #pragma unroll
        for (int s = 0; s < 4; s++) { rs[tid >> 5][s] = ls[s]; rq[tid >> 5][s] = lq[s]; }
    }
    __syncthreads();
    if (tid < 4) {
        float s = 0.0f, q = 0.0f;
        #pragma unroll
        for (int w = 0; w < 8; w++) { s += rs[w][tid]; q += rq[w][tid]; }
        float mean = s * (1.0f / 4096.0f);
        float var = q * (1.0f / 4096.0f) - mean * mean;
        sM[tid] = mean;
        sS[tid] = rsqrtf(var + 1e-5f);
    }
    __syncthreads();
    #pragma unroll
    for (int s = 0; s < 4; s++) {
        const float mean = sM[s], scale = sS[s];
        float2* orow = (float2*)(g_T + ((size_t)(bp * NHF + hi0 + s) << 12));
        #pragma unroll
        for (int r = 0; r < 8; r++) {
            int n = tid + (r << 8);
            float2 v = bB[SW(n, s)];
            orow[n] = make_float2((v.x - mean) * scale, (v.y - mean) * scale);
        }
    }
}

// ---------------- kernel 5: (t b) h n -> b h (n t) ----------------
__global__ __launch_bounds__(256) void k_out(float* __restrict__ out) {
    __shared__ float s[256 * 17];
    const int tid = threadIdx.x;
    const int blk = blockIdx.x;
    const int nc = blk & 15;
    const int bh = blk >> 4;
    const int hi = bh & (NHF - 1);
    const int bi = bh >> 7;
    #pragma unroll
    for (int ti = 0; ti < 16; ti++) {
        s[tid * 17 + ti] = g_T[((size_t)((ti * NB + bi) * NHF + hi) << 12) + nc * 256 + tid];
    }
    __syncthreads();
    float* obase = out + (size_t)bh * NSEG + nc * 4096;
    #pragma unroll
    for (int i = 0; i < 16; i++) {
        int u = tid + (i << 8);
        obase[u] = s[(u >> 4) * 17 + (u & 15)];
    }
}

// ---------------- launch ----------------
extern "C" void kernel_launch(void* const* d_in, const int* in_sizes, int n_in,
                              void* d_out, int out_size) {
    const float* X = (const float*)d_in[0];
    const float* F = (const float*)d_in[1];
    if (n_in >= 2 && in_sizes[0] < in_sizes[1]) {
        const float* t = X; X = F; F = t;
    }
    float* out = (float*)d_out;

    const int SMEM = 2 * 8192 * sizeof(float2);   // 131072
    cudaFuncSetAttribute(k_fwd_x, cudaFuncAttributeMaxDynamicSharedMemorySize, SMEM);
    cudaFuncSetAttribute(k_fwd_f, cudaFuncAttributeMaxDynamicSharedMemorySize, SMEM);
    cudaFuncSetAttribute(k_inv,   cudaFuncAttributeMaxDynamicSharedMemorySize, SMEM);

    k_twid<<<16, 256>>>();
    k_fwd_x<<<NB * 16 * 16, 256, SMEM>>>(X);      // 2048 blocks, 4 ch each
    k_fwd_f<<<NC * 32, 256, SMEM>>>(F);           // 2048 blocks, 4 heads each
    k_gemm<<<dim3(2, NFRQ), 256>>>();             // 4098 blocks
    k_inv<<<BP * 32, 256, SMEM>>>();              // 4096 blocks, 4 heads each
    k_out<<<NB * NHF * 16, 256>>>(out);           // 16384 blocks
}

// round 6
// speedup vs baseline: 1.2217x; 1.0043x over previous
#include <cuda_runtime.h>
#include <math.h>

// ---------------- problem constants ----------------
#define NFFT   4096
#define NH     2048
#define NFRQ   2049
#define BP     128
#define NC     64
#define NHF    128
#define TT     16
#define NB     8
#define NSEG   65536
#define FLT_LEN 1023

// ---------------- scratch ----------------
__device__ float2 g_U[(size_t)NFRQ * BP * NC];    // [k][b'][c]
__device__ float2 g_V[(size_t)NFRQ * NC * NHF];   // [k][c][h] (conj)
__device__ float2 g_Y[(size_t)NFRQ * BP * NHF];   // [k][b'][h]
__device__ float  g_T[(size_t)BP * NHF * NFFT];   // staging [b'][h][n]
__device__ float2 g_tw2048[NH];
__device__ float2 g_tw4096[NH];

// ---------------- helpers ----------------
// swizzled index for interleaved-4 buffers: float2 slot for (k, s)
__device__ __forceinline__ int SW(int k, int s) {
    int x = ((k >> 2) ^ (k >> 6)) & 1;                 // -> bit0
    x |= (((k >> 3) ^ (k >> 6)) & 1) << 1;             // -> bit1
    x |= (((k >> 3) ^ (k >> 5)) & 1) << 2;             // -> bit2
    x |= (((k >> 4) ^ (k >> 6)) & 1) << 3;             // -> bit3
    return ((k << 2) | s) ^ x;
}

__device__ __forceinline__ float2 cadd(float2 a, float2 b){return make_float2(a.x+b.x, a.y+b.y);}
__device__ __forceinline__ float2 csub(float2 a, float2 b){return make_float2(a.x-b.x, a.y-b.y);}
__device__ __forceinline__ float2 cmulf(float2 a, float2 b){
    return make_float2(fmaf(a.x, b.x, -a.y*b.y), fmaf(a.x, b.y, a.y*b.x));
}
template<int INV> __device__ __forceinline__ float2 mulI(float2 a){
    return INV ? make_float2(-a.y, a.x) : make_float2(a.y, -a.x);
}
template<int INV> __device__ __forceinline__ float2 twld(const float2* __restrict__ t, int i){
    float2 w = __ldg(&t[i]);
    if (INV) w.y = -w.y;
    return w;
}

template<int INV>
__device__ __forceinline__ void dft8(const float2* a, float2* B) {
    const float r = 0.70710678118654752440f;
    float2 e0=cadd(a[0],a[4]), e1=csub(a[0],a[4]);
    float2 e2=cadd(a[2],a[6]), e3=mulI<INV>(csub(a[2],a[6]));
    float2 E0=cadd(e0,e2), E2=csub(e0,e2), E1=cadd(e1,e3), E3=csub(e1,e3);
    float2 o0=cadd(a[1],a[5]), o1=csub(a[1],a[5]);
    float2 o2=cadd(a[3],a[7]), o3=mulI<INV>(csub(a[3],a[7]));
    float2 O0=cadd(o0,o2), O2=csub(o0,o2), O1=cadd(o1,o3), O3=csub(o1,o3);
    float2 w1o, w3o;
    if (!INV) {
        w1o = make_float2(r*(O1.x+O1.y), r*(O1.y-O1.x));
        w3o = make_float2(r*(O3.y-O3.x), -r*(O3.x+O3.y));
    } else {
        w1o = make_float2(r*(O1.x-O1.y), r*(O1.y+O1.x));
        w3o = make_float2(-r*(O3.x+O3.y), r*(O3.x-O3.y));
    }
    float2 w2o = mulI<INV>(O2);
    B[0]=cadd(E0,O0); B[4]=csub(E0,O0);
    B[1]=cadd(E1,w1o); B[5]=csub(E1,w1o);
    B[2]=cadd(E2,w2o); B[6]=csub(E2,w2o);
    B[3]=cadd(E3,w3o); B[7]=csub(E3,w3o);
}

// Interleaved x4 Stockham FFT, N=2048=8*8*8*4, 256 threads.
// Input in bA at SW(n,s). Output in bA at SW(k,s), natural order.
template<int INV>
__device__ void fft2048x4(float2* bA, float2* bB, const float2* __restrict__ twg, int tid) {
    { // S0: A->B  read tid+256j, write 8*tid+j, tw j*tid
        float2 w[7];
        #pragma unroll
        for (int j=1;j<8;j++) w[j-1] = twld<INV>(twg, j*tid);
        #pragma unroll
        for (int s=0;s<4;s++) {
            float2 a[8], B[8];
            #pragma unroll
            for (int j=0;j<8;j++) a[j] = bA[SW(tid + (j<<8), s)];
            dft8<INV>(a,B);
            #pragma unroll
            for (int j=1;j<8;j++) B[j] = cmulf(B[j], w[j-1]);
            #pragma unroll
            for (int j=0;j<8;j++) bB[SW((tid<<3) + j, s)] = B[j];
        }
    }
    __syncthreads();
    { // S1: B->A  write q+64p+8j, tw j*8p
        const int p = tid>>3, q = tid&7, ps = p<<3, base = q + (p<<6);
        float2 w[7];
        #pragma unroll
        for (int j=1;j<8;j++) w[j-1] = twld<INV>(twg, j*ps);
        #pragma unroll
        for (int s=0;s<4;s++) {
            float2 a[8], B[8];
            #pragma unroll
            for (int j=0;j<8;j++) a[j] = bB[SW(tid + (j<<8), s)];
            dft8<INV>(a,B);
            #pragma unroll
            for (int j=1;j<8;j++) B[j] = cmulf(B[j], w[j-1]);
            #pragma unroll
            for (int j=0;j<8;j++) bA[SW(base + (j<<3), s)] = B[j];
        }
    }
    __syncthreads();
    { // S2: A->B  write q+512p+64j, tw j*64p
        const int p = tid>>6, q = tid&63, ps = p<<6, base = q + (p<<9);
        float2 w[7];
        #pragma unroll
        for (int j=1;j<8;j++) w[j-1] = twld<INV>(twg, j*ps);
        #pragma unroll
        for (int s=0;s<4;s++) {
            float2 a[8], B[8];
            #pragma unroll
            for (int j=0;j<8;j++) a[j] = bA[SW(tid + (j<<8), s)];
            dft8<INV>(a,B);
            #pragma unroll
            for (int j=1;j<8;j++) B[j] = cmulf(B[j], w[j-1]);
            #pragma unroll
            for (int j=0;j<8;j++) bB[SW(base + (j<<6), s)] = B[j];
        }
    }
    __syncthreads();
    // S3: radix-4 B->A (no twiddles)
    #pragma unroll
    for (int e=0;e<2;e++) {
        const int idx = tid + (e<<8);
        #pragma unroll
        for (int s=0;s<4;s++) {
            float2 c0=bB[SW(idx,s)], c1=bB[SW(idx+512,s)], c2=bB[SW(idx+1024,s)], c3=bB[SW(idx+1536,s)];
            float2 t0=cadd(c0,c2), t1=csub(c0,c2);
            float2 t2=cadd(c1,c3), t3=mulI<INV>(csub(c1,c3));
            bA[SW(idx,s)]      = cadd(t0,t2);
            bA[SW(idx+512,s)]  = cadd(t1,t3);
            bA[SW(idx+1024,s)] = csub(t0,t2);
            bA[SW(idx+1536,s)] = csub(t1,t3);
        }
    }
    __syncthreads();
}

// rfft post-combine: given Z[k], Z[(N-k)%N] of packed FFT -> U[k]
__device__ __forceinline__ float2 rpost(float2 Zk, float2 Zc, float2 W) {
    Zc.y = -Zc.y;
    float2 Xe = make_float2(0.5f*(Zk.x+Zc.x), 0.5f*(Zk.y+Zc.y));
    float dx = Zk.x - Zc.x, dy = Zk.y - Zc.y;
    float2 Xo = make_float2(0.5f*dy, -0.5f*dx);
    float2 WXo = cmulf(W, Xo);
    return make_float2(Xe.x + WXo.x, Xe.y + WXo.y);
}

// ---------------- kernel 0: twiddles ----------------
__global__ void k_twid() {
    int i = blockIdx.x * 256 + threadIdx.x;
    float s, c;
    if (i < NH) {
        sincospif(-(float)i / 1024.0f, &s, &c);
        g_tw2048[i] = make_float2(c, s);
    } else {
        int k = i - NH;
        sincospif(-(float)k / 2048.0f, &s, &c);
        g_tw4096[k] = make_float2(c, s);
    }
}

// ---------------- kernel 1: forward rfft of X, 4 channels interleaved ----------------
__global__ __launch_bounds__(256) void k_fwd_x(const float* __restrict__ X) {
    extern __shared__ float2 dsm[];
    float2* bA = dsm;
    float2* bB = dsm + 8192;
    const int tid = threadIdx.x;
    const int blk = blockIdx.x;            // ((bi*16 + cq)<<4) + ti
    const int ti  = blk & 15;
    const int bcq = blk >> 4;
    const int cq  = bcq & 15;
    const int bi  = bcq >> 4;
    const int bp  = ti * NB + bi;
    const int ci0 = cq * 4;
    const float* base = X + (size_t)(bi * NC + ci0) * NSEG;

    #pragma unroll
    for (int r = 0; r < 8; r++) {
        int n = tid + (r << 8);
        int off = (n << 5) + ti;
        #pragma unroll
        for (int s = 0; s < 4; s++) {
            float e = __ldg(base + (size_t)s * NSEG + off);
            float o = __ldg(base + (size_t)s * NSEG + off + 16);
            bA[SW(n, s)] = make_float2(e, o);
        }
    }
    __syncthreads();
    fft2048x4<0>(bA, bB, g_tw2048, tid);

    const size_t gbase = (size_t)bp * NC + ci0;
    #pragma unroll
    for (int r = 0; r < 8; r++) {
        int k = tid + (r << 8);
        int km = (NH - k) & (NH - 1);
        float2 W = __ldg(&g_tw4096[k]);
        float2 v[4];
        #pragma unroll
        for (int s = 0; s < 4; s++)
            v[s] = rpost(bA[SW(k, s)], bA[SW(km, s)], W);
        float4* dst = (float4*)(g_U + (size_t)k * (BP*NC) + gbase);
        dst[0] = make_float4(v[0].x, v[0].y, v[1].x, v[1].y);
        dst[1] = make_float4(v[2].x, v[2].y, v[3].x, v[3].y);
        if (k == 0) {
            float2 nv[4];
            #pragma unroll
            for (int s = 0; s < 4; s++) {
                float2 Z0 = bA[SW(0, s)];
                nv[s] = make_float2(Z0.x - Z0.y, 0.0f);
            }
            float4* nd = (float4*)(g_U + (size_t)NH * (BP*NC) + gbase);
            nd[0] = make_float4(nv[0].x, nv[0].y, nv[1].x, nv[1].y);
            nd[1] = make_float4(nv[2].x, nv[2].y, nv[3].x, nv[3].y);
        }
    }
}

// ---------------- kernel 2: conj(rfft(filters)), 4 heads interleaved ----------------
__global__ __launch_bounds__(256) void k_fwd_f(const float* __restrict__ F) {
    extern __shared__ float2 dsm[];
    float2* bA = dsm;
    float2* bB = dsm + 8192;
    const int tid = threadIdx.x;
    const int blk = blockIdx.x;            // ci*32 + hq
    const int hq = blk & 31;
    const int ci = blk >> 5;
    const int hi0 = hq * 4;

    #pragma unroll
    for (int r = 0; r < 8; r++) {
        int n = tid + (r << 8);
        int i0 = 2 * n, i1 = 2 * n + 1;
        #pragma unroll
        for (int s = 0; s < 4; s++) {
            const float* row = F + ((size_t)(hi0 + s) * NC + ci) * FLT_LEN;
            float e = (i0 < FLT_LEN) ? __ldg(row + i0) : 0.0f;
            float o = (i1 < FLT_LEN) ? __ldg(row + i1) : 0.0f;
            bA[SW(n, s)] = make_float2(e, o);
        }
    }
    __syncthreads();
    fft2048x4<0>(bA, bB, g_tw2048, tid);

    const size_t gbase = (size_t)ci * NHF + hi0;
    #pragma unroll
    for (int r = 0; r < 8; r++) {
        int k = tid + (r << 8);
        int km = (NH - k) & (NH - 1);
        float2 W = __ldg(&g_tw4096[k]);
        float2 v[4];
        #pragma unroll
        for (int s = 0; s < 4; s++) {
            float2 u = rpost(bA[SW(k, s)], bA[SW(km, s)], W);
            v[s] = make_float2(u.x, -u.y);     // conj
        }
        float4* dst = (float4*)(g_V + (size_t)k * (NC*NHF) + gbase);
        dst[0] = make_float4(v[0].x, v[0].y, v[1].x, v[1].y);
        dst[1] = make_float4(v[2].x, v[2].y, v[3].x, v[3].y);
        if (k == 0) {
            float2 nv[4];
            #pragma unroll
            for (int s = 0; s < 4; s++) {
                float2 Z0 = bA[SW(0, s)];
                nv[s] = make_float2(Z0.x - Z0.y, 0.0f);
            }
            float4* nd = (float4*)(g_V + (size_t)NH * (NC*NHF) + gbase);
            nd[0] = make_float4(nv[0].x, nv[0].y, nv[1].x, nv[1].y);
            nd[1] = make_float4(nv[2].x, nv[2].y, nv[3].x, nv[3].y);
        }
    }
}

// ---------------- kernel 3: per-frequency complex GEMM (unchanged) ----------------
__device__ __forceinline__ unsigned long long splat2(float x) {
    unsigned long long r;
    asm("mov.b64 %0, {%1, %1};" : "=l"(r) : "f"(x));
    return r;
}
__device__ __forceinline__ void fma2(unsigned long long& d, unsigned long long a, unsigned long long b) {
    asm("fma.rn.f32x2 %0, %1, %2, %0;" : "+l"(d) : "l"(a), "l"(b));
}
#define CK 8

__global__ __launch_bounds__(256, 2) void k_gemm() {
    __shared__ float2 sU[64 * 65];
    __shared__ float2 sVr[CK * 128];
    __shared__ float2 sVs[CK * 128];
    const int k = blockIdx.y;
    const int half = blockIdx.x;
    const int tid = threadIdx.x;
    const int tx = tid & 15, ty = tid >> 4;

    const float2* Uk = g_U + (size_t)k * (BP*NC) + (size_t)half * (64*NC);
    #pragma unroll
    for (int r = 0; r < 16; r++) {
        int i = tid + (r << 8);
        int brow = i >> 6, c = i & 63;
        sU[c * 65 + brow] = __ldg(&Uk[i]);
    }

    const float4* Vk = (const float4*)(g_V + (size_t)k * (NC*NHF));
    float4 p0 = __ldg(&Vk[tid * 2]);
    float4 p1 = __ldg(&Vk[tid * 2 + 1]);

    unsigned long long acc[4][8];
    #pragma unroll
    for (int i = 0; i < 4; i++)
        #pragma unroll
        for (int j = 0; j < 8; j++) acc[i][j] = 0ull;

    #pragma unroll 1
    for (int ch = 0; ch < NC / CK; ch++) {
        __syncthreads();
        {
            const int i0 = tid * 4;
            sVr[i0]     = make_float2(p0.x, p0.y);
            sVr[i0 + 1] = make_float2(p0.z, p0.w);
            sVr[i0 + 2] = make_float2(p1.x, p1.y);
            sVr[i0 + 3] = make_float2(p1.z, p1.w);
            sVs[i0]     = make_float2(-p0.y, p0.x);
            sVs[i0 + 1] = make_float2(-p0.w, p0.z);
            sVs[i0 + 2] = make_float2(-p1.y, p1.x);
            sVs[i0 + 3] = make_float2(-p1.w, p1.z);
        }
        __syncthreads();
        if (ch < NC / CK - 1) {
            p0 = __ldg(&Vk[(ch + 1) * 512 + tid * 2]);
            p1 = __ldg(&Vk[(ch + 1) * 512 + tid * 2 + 1]);
        }
        #pragma unroll
        for (int cc = 0; cc < CK; cc++) {
            const int c = ch * CK + cc;
            unsigned long long ax[4], ay[4];
            #pragma unroll
            for (int i = 0; i < 4; i++) {
                float2 a = sU[c * 65 + ty + (i << 4)];
                ax[i] = splat2(a.x);
                ay[i] = splat2(a.y);
            }
            #pragma unroll
            for (int j = 0; j < 8; j++) {
                unsigned long long br = *(const unsigned long long*)&sVr[cc * 128 + tx + (j << 4)];
                unsigned long long bs = *(const unsigned long long*)&sVs[cc * 128 + tx + (j << 4)];
                #pragma unroll
                for (int i = 0; i < 4; i++) {
                    fma2(acc[i][j], ax[i], br);
                    fma2(acc[i][j], ay[i], bs);
                }
            }
        }
    }

    float2* Yk = g_Y + (size_t)k * (BP*NHF) + (size_t)half * (64*NHF);
    #pragma unroll
    for (int i = 0; i < 4; i++) {
        int row = ty + (i << 4);
        #pragma unroll
        for (int j = 0; j < 8; j++) {
            float rx, ry;
            asm("mov.b64 {%0, %1}, %2;" : "=f"(rx), "=f"(ry) : "l"(acc[i][j]));
            Yk[row * NHF + tx + (j << 4)] = make_float2(rx, ry);
        }
    }
}

// ---------------- kernel 4: irfft + log1p + InstanceNorm, 4 heads interleaved ----------------
__global__ __launch_bounds__(256) void k_inv() {
    extern __shared__ float2 dsm[];
    float2* bA = dsm;
    float2* bB = dsm + 8192;
    __shared__ float rs[8][4], rq[8][4];
    __shared__ float sM[4], sS[4];
    const int tid = threadIdx.x;
    const int blk = blockIdx.x;            // bp*32 + hq
    const int hq = blk & 31;
    const int bp = blk >> 5;
    const int hi0 = hq * 4;

    const float2* Ybase = g_Y + (size_t)bp * NHF + hi0;
    #pragma unroll
    for (int r = 0; r < 8; r++) {
        int k = tid + (r << 8);
        const float4* Yk4 = (const float4*)(Ybase + (size_t)k * (BP*NHF));
        const float4* Ym4 = (const float4*)(Ybase + (size_t)(NH - k) * (BP*NHF));
        float4 a0 = __ldg(&Yk4[0]), a1 = __ldg(&Yk4[1]);
        float4 m0 = __ldg(&Ym4[0]), m1 = __ldg(&Ym4[1]);
        float2 t = __ldg(&g_tw4096[k]);
        float c = t.x, sn = -t.y;              // exp(+2pi i k/4096)
        float2 Yk[4] = { make_float2(a0.x,a0.y), make_float2(a0.z,a0.w),
                         make_float2(a1.x,a1.y), make_float2(a1.z,a1.w) };
        float2 Ym[4] = { make_float2(m0.x,m0.y), make_float2(m0.z,m0.w),
                         make_float2(m1.x,m1.y), make_float2(m1.z,m1.w) };
        #pragma unroll
        for (int s = 0; s < 4; s++) {
            float2 yk = Yk[s], ym = Ym[s];
            ym.y = -ym.y;
            float2 Xe = make_float2(0.5f*(yk.x+ym.x), 0.5f*(yk.y+ym.y));
            float dx = yk.x - ym.x, dy = yk.y - ym.y;
            float Xox = 0.5f * (c*dx - sn*dy);
            float Xoy = 0.5f * (c*dy + sn*dx);
            bA[SW(k, s)] = make_float2(Xe.x - Xoy, Xe.y + Xox);
        }
    }
    __syncthreads();
    fft2048x4<1>(bA, bB, g_tw2048, tid);

    const float inv = 1.0f / 2048.0f;
    float ls[4] = {0,0,0,0}, lq[4] = {0,0,0,0};
    #pragma unroll
    for (int r = 0; r < 8; r++) {
        int n = tid + (r << 8);
        #pragma unroll
        for (int s = 0; s < 4; s++) {
            float2 zz = bA[SW(n, s)];
            float v0 = __logf(1.0f + fabsf(zz.x * inv));
            float v1 = __logf(1.0f + fabsf(zz.y * inv));
            bB[SW(n, s)] = make_float2(v0, v1);
            ls[s] += v0 + v1;
            lq[s] = fmaf(v0, v0, lq[s]);
            lq[s] = fmaf(v1, v1, lq[s]);
        }
    }
    #pragma unroll
    for (int o = 16; o; o >>= 1) {
        #pragma unroll
        for (int s = 0; s < 4; s++) {
            ls[s] += __shfl_xor_sync(0xffffffffu, ls[s], o);
            lq[s] += __shfl_xor_sync(0xffffffffu, lq[s], o);
        }
    }
    if ((tid & 31) == 0) {
        #pragma unroll
        for (int s = 0; s < 4; s++) { rs[tid >> 5][s] = ls[s]; rq[tid >> 5][s] = lq[s]; }
    }
    __syncthreads();
    if (tid < 4) {
        float s = 0.0f, q = 0.0f;
        #pragma unroll
        for (int w = 0; w < 8; w++) { s += rs[w][tid]; q += rq[w][tid]; }
        float mean = s * (1.0f / 4096.0f);
        float var = q * (1.0f / 4096.0f) - mean * mean;
        sM[tid] = mean;
        sS[tid] = rsqrtf(var + 1e-5f);
    }
    __syncthreads();
    #pragma unroll
    for (int s = 0; s < 4; s++) {
        const float mean = sM[s], scale = sS[s];
        float2* orow = (float2*)(g_T + ((size_t)(bp * NHF + hi0 + s) << 12));
        #pragma unroll
        for (int r = 0; r < 8; r++) {
            int n = tid + (r << 8);
            float2 v = bB[SW(n, s)];
            orow[n] = make_float2((v.x - mean) * scale, (v.y - mean) * scale);
        }
    }
}

// ---------------- kernel 5: (t b) h n -> b h (n t) ----------------
__global__ __launch_bounds__(256) void k_out(float* __restrict__ out) {
    __shared__ float s[256 * 17];
    const int tid = threadIdx.x;
    const int blk = blockIdx.x;
    const int nc = blk & 15;
    const int bh = blk >> 4;
    const int hi = bh & (NHF - 1);
    const int bi = bh >> 7;
    #pragma unroll
    for (int ti = 0; ti < 16; ti++) {
        s[tid * 17 + ti] = g_T[((size_t)((ti * NB + bi) * NHF + hi) << 12) + nc * 256 + tid];
    }
    __syncthreads();
    float* obase = out + (size_t)bh * NSEG + nc * 4096;
    #pragma unroll
    for (int i = 0; i < 16; i++) {
        int u = tid + (i << 8);
        obase[u] = s[(u >> 4) * 17 + (u & 15)];
    }
}

// ---------------- launch ----------------
extern "C" void kernel_launch(void* const* d_in, const int* in_sizes, int n_in,
                              void* d_out, int out_size) {
    const float* X = (const float*)d_in[0];
    const float* F = (const float*)d_in[1];
    if (n_in >= 2 && in_sizes[0] < in_sizes[1]) {
        const float* t = X; X = F; F = t;
    }
    float* out = (float*)d_out;

    const int SMEM = 2 * 8192 * sizeof(float2);   // 131072
    cudaFuncSetAttribute(k_fwd_x, cudaFuncAttributeMaxDynamicSharedMemorySize, SMEM);
    cudaFuncSetAttribute(k_fwd_f, cudaFuncAttributeMaxDynamicSharedMemorySize, SMEM);
    cudaFuncSetAttribute(k_inv,   cudaFuncAttributeMaxDynamicSharedMemorySize, SMEM);

    k_twid<<<16, 256>>>();
    k_fwd_x<<<NB * 16 * 16, 256, SMEM>>>(X);      // 2048 blocks, 4 ch each
    k_fwd_f<<<NC * 32, 256, SMEM>>>(F);           // 2048 blocks, 4 heads each
    k_gemm<<<dim3(2, NFRQ), 256>>>();             // 4098 blocks
    k_inv<<<BP * 32, 256, SMEM>>>();              // 4096 blocks, 4 heads each
    k_out<<<NB * NHF * 16, 256>>>(out);           // 16384 blocks
}